// round 1
// baseline (speedup 1.0000x reference)
#include <cuda_runtime.h>
#include <math_constants.h>

// Problem shapes (from reference setup_inputs)
#define B_DIM 8
#define C_IN 32
#define C_OUT 32
#define P_DIM 262144
#define K_SH 81          // (MAX_L+1)^2, MAX_L=8
#define N_ROWS (B_DIM * C_IN)          // 256
#define SPLITS 32
#define CHUNK (P_DIM / SPLITS)         // 8192 elements per block
#define THREADS 256

// Scratch (no cudaMalloc allowed)
__device__ float g_partials[N_ROWS * SPLITS];
__device__ float g_s[N_ROWS];

// ---------------------------------------------------------------------------
// Phase 1: per-(row, split) partial sums. Deterministic tree reduction.
// ---------------------------------------------------------------------------
__global__ void __launch_bounds__(THREADS) reduce_kernel(const float* __restrict__ in) {
    const int row   = blockIdx.x / SPLITS;
    const int split = blockIdx.x % SPLITS;
    const float4* __restrict__ p =
        reinterpret_cast<const float4*>(in + (size_t)row * P_DIM + (size_t)split * CHUNK);

    // CHUNK/4 = 2048 float4 per block; 256 threads * 8 float4 each (strided, coalesced)
    float acc = 0.0f;
    #pragma unroll
    for (int j = 0; j < 8; ++j) {
        float4 v = p[threadIdx.x + j * THREADS];
        acc += (v.x + v.y) + (v.z + v.w);
    }

    // warp reduce
    #pragma unroll
    for (int off = 16; off > 0; off >>= 1)
        acc += __shfl_xor_sync(0xFFFFFFFFu, acc, off);

    __shared__ float warp_sums[THREADS / 32];
    const int lane = threadIdx.x & 31;
    const int wid  = threadIdx.x >> 5;
    if (lane == 0) warp_sums[wid] = acc;
    __syncthreads();

    if (wid == 0) {
        float s = (lane < THREADS / 32) ? warp_sums[lane] : 0.0f;
        #pragma unroll
        for (int off = 4; off > 0; off >>= 1)
            s += __shfl_xor_sync(0xFFFFFFFFu, s, off);
        if (lane == 0) g_partials[blockIdx.x] = s;
    }
}

// ---------------------------------------------------------------------------
// Phase 2: fold the SPLITS partials of each row into g_s[row].
// One block, 256 threads = one thread per row.
// ---------------------------------------------------------------------------
__global__ void __launch_bounds__(N_ROWS) combine_kernel() {
    const int row = threadIdx.x;
    float s = 0.0f;
    #pragma unroll
    for (int j = 0; j < SPLITS; ++j)
        s += g_partials[row * SPLITS + j];
    g_s[row] = s;
}

// ---------------------------------------------------------------------------
// Phase 3: out[b,o,k] = Y[k] * sum_i coeff[o,i,k] * s[b,i]
// Y[k] nonzero only when k == l*l + l (m == 0): value sqrt((2l+1)/(4*pi)).
// Grid: one block per k (81 blocks), 256 threads = one per (b,o).
// ---------------------------------------------------------------------------
__global__ void __launch_bounds__(B_DIM * C_OUT) epilogue_kernel(
        const float* __restrict__ coeff, float* __restrict__ out) {
    const int k = blockIdx.x;            // 0..80
    const int bo = threadIdx.x;          // 0..255
    const int b = bo / C_OUT;
    const int o = bo % C_OUT;

    // l = floor(sqrt(k)); small integer search (k <= 80)
    int l = 0;
    while ((l + 1) * (l + 1) <= k) ++l;
    const int m = k - l * l - l;         // m index relative to 0

    float y = 0.0f;
    if (m == 0)
        y = sqrtf((2.0f * l + 1.0f) / (4.0f * CUDART_PI_F));

    float acc = 0.0f;
    if (m == 0) {
        const float* srow = &g_s[b * C_IN];
        #pragma unroll
        for (int i = 0; i < C_IN; ++i)
            acc += coeff[((size_t)o * C_IN + i) * K_SH + k] * srow[i];
    }
    out[((size_t)b * C_OUT + o) * K_SH + k] = y * acc;
}

// ---------------------------------------------------------------------------
extern "C" void kernel_launch(void* const* d_in, const int* in_sizes, int n_in,
                              void* d_out, int out_size) {
    const float* input = (const float*)d_in[0];   // [B, C_in, P]
    const float* coeff = (const float*)d_in[1];   // [C_out, C_in, K]
    float* out = (float*)d_out;                   // [B, C_out, K]

    reduce_kernel<<<N_ROWS * SPLITS, THREADS>>>(input);
    combine_kernel<<<1, N_ROWS>>>();
    epilogue_kernel<<<K_SH, B_DIM * C_OUT>>>(coeff, out);
}

// round 4
// speedup vs baseline: 1.0883x; 1.0883x over previous
#include <cuda_runtime.h>
#include <math_constants.h>

// Problem shapes (from reference setup_inputs)
#define B_DIM 8
#define C_IN 32
#define C_OUT 32
#define P_DIM 262144
#define K_SH 81                         // (MAX_L+1)^2, MAX_L=8
#define N_ROWS (B_DIM * C_IN)           // 256
#define SPLITS 4
#define CHUNK (P_DIM / SPLITS)          // 65536 elements per block (256 KB)
#define THREADS 256

// Scratch (no cudaMalloc allowed)
__device__ float g_partials[N_ROWS * SPLITS];   // 1024 floats

// ---------------------------------------------------------------------------
// Phase 1: per-(row, split) partial sums. 1024 blocks = ONE full-chip wave.
// Each thread: 64 float4 loads (16K float4 per block / 256 threads),
// 4 independent accumulators, 16 loads in flight per unrolled batch.
// ---------------------------------------------------------------------------
__global__ void __launch_bounds__(THREADS) reduce_kernel(const float* __restrict__ in) {
    const int row   = blockIdx.x / SPLITS;
    const int split = blockIdx.x % SPLITS;
    const float4* __restrict__ p =
        reinterpret_cast<const float4*>(in + (size_t)row * P_DIM + (size_t)split * CHUNK);

    float a0 = 0.f, a1 = 0.f, a2 = 0.f, a3 = 0.f;
    // 64 iterations total; unroll 4 outer -> 16 independent LDG.128 per batch
    #pragma unroll 4
    for (int jo = 0; jo < 16; ++jo) {
        float4 v0 = p[threadIdx.x + (jo * 4 + 0) * THREADS];
        float4 v1 = p[threadIdx.x + (jo * 4 + 1) * THREADS];
        float4 v2 = p[threadIdx.x + (jo * 4 + 2) * THREADS];
        float4 v3 = p[threadIdx.x + (jo * 4 + 3) * THREADS];
        a0 += (v0.x + v0.y) + (v0.z + v0.w);
        a1 += (v1.x + v1.y) + (v1.z + v1.w);
        a2 += (v2.x + v2.y) + (v2.z + v2.w);
        a3 += (v3.x + v3.y) + (v3.z + v3.w);
    }
    float acc = (a0 + a1) + (a2 + a3);

    // warp reduce
    #pragma unroll
    for (int off = 16; off > 0; off >>= 1)
        acc += __shfl_xor_sync(0xFFFFFFFFu, acc, off);

    __shared__ float warp_sums[THREADS / 32];
    const int lane = threadIdx.x & 31;
    const int wid  = threadIdx.x >> 5;
    if (lane == 0) warp_sums[wid] = acc;
    __syncthreads();

    if (wid == 0) {
        float s = (lane < THREADS / 32) ? warp_sums[lane] : 0.0f;
        #pragma unroll
        for (int off = 4; off > 0; off >>= 1)
            s += __shfl_xor_sync(0xFFFFFFFFu, s, off);
        if (lane == 0) g_partials[blockIdx.x] = s;
    }
}

// ---------------------------------------------------------------------------
// Phase 2 (fused combine + epilogue):
// out[b,o,k] = Y[k] * sum_i coeff[o,i,k] * s[b,i],  s[b,i] folded from
// g_partials (1024 floats, L2-hot) inside every block.
// Grid: one block per k (81 blocks), 256 threads = one per (b,o).
// Y[k] nonzero only when m == 0 (k == l*l + l): sqrt((2l+1)/(4*pi)).
// ---------------------------------------------------------------------------
__global__ void __launch_bounds__(B_DIM * C_OUT) epilogue_kernel(
        const float* __restrict__ coeff, float* __restrict__ out) {
    __shared__ float s_rows[N_ROWS];

    // Fold SPLITS partials per row: thread t handles row t.
    {
        const int row = threadIdx.x;
        float s = 0.0f;
        #pragma unroll
        for (int j = 0; j < SPLITS; ++j)
            s += g_partials[row * SPLITS + j];
        s_rows[row] = s;
    }
    __syncthreads();

    const int k  = blockIdx.x;           // 0..80
    const int bo = threadIdx.x;          // 0..255
    const int b  = bo / C_OUT;
    const int o  = bo % C_OUT;

    // l = floor(sqrt(k)); tiny integer search (k <= 80)
    int l = 0;
    while ((l + 1) * (l + 1) <= k) ++l;
    const int m = k - l * l - l;

    float result = 0.0f;
    if (m == 0) {
        const float y = sqrtf((2.0f * l + 1.0f) / (4.0f * CUDART_PI_F));
        const float* srow = &s_rows[b * C_IN];
        float acc = 0.0f;
        #pragma unroll
        for (int i = 0; i < C_IN; ++i)
            acc += coeff[((size_t)o * C_IN + i) * K_SH + k] * srow[i];
        result = y * acc;
    }
    out[((size_t)b * C_OUT + o) * K_SH + k] = result;
}

// ---------------------------------------------------------------------------
extern "C" void kernel_launch(void* const* d_in, const int* in_sizes, int n_in,
                              void* d_out, int out_size) {
    const float* input = (const float*)d_in[0];   // [B, C_in, P]
    const float* coeff = (const float*)d_in[1];   // [C_out, C_in, K]
    float* out = (float*)d_out;                   // [B, C_out, K]

    reduce_kernel<<<N_ROWS * SPLITS, THREADS>>>(input);
    epilogue_kernel<<<K_SH, B_DIM * C_OUT>>>(coeff, out);
}

// round 7
// speedup vs baseline: 1.1429x; 1.0501x over previous
#include <cuda_runtime.h>
#include <math_constants.h>

// Problem shapes (from reference setup_inputs)
#define B_DIM 8
#define C_IN 32
#define C_OUT 32
#define P_DIM 262144
#define K_SH 81                         // (MAX_L+1)^2, MAX_L=8
#define N_ROWS (B_DIM * C_IN)           // 256
#define SPLITS 4
#define CHUNK (P_DIM / SPLITS)          // 65536 elements per block (256 KB)
#define THREADS 256
#define N_RED_BLOCKS (N_ROWS * SPLITS)  // 1024

// Scratch (no cudaMalloc allowed)
__device__ float g_partials[N_RED_BLOCKS];

// ---------------------------------------------------------------------------
// Phase 1: per-(row, split) partial sums. 1024 blocks = one full-chip wave.
// Each thread: 64 float4 loads, 4 independent accumulators.
// ---------------------------------------------------------------------------
__global__ void __launch_bounds__(THREADS) reduce_kernel(const float* __restrict__ in) {
    const int row   = blockIdx.x / SPLITS;
    const int split = blockIdx.x % SPLITS;
    const float4* __restrict__ p =
        reinterpret_cast<const float4*>(in + (size_t)row * P_DIM + (size_t)split * CHUNK);

    float a0 = 0.f, a1 = 0.f, a2 = 0.f, a3 = 0.f;
    #pragma unroll 4
    for (int jo = 0; jo < 16; ++jo) {
        float4 v0 = p[threadIdx.x + (jo * 4 + 0) * THREADS];
        float4 v1 = p[threadIdx.x + (jo * 4 + 1) * THREADS];
        float4 v2 = p[threadIdx.x + (jo * 4 + 2) * THREADS];
        float4 v3 = p[threadIdx.x + (jo * 4 + 3) * THREADS];
        a0 += (v0.x + v0.y) + (v0.z + v0.w);
        a1 += (v1.x + v1.y) + (v1.z + v1.w);
        a2 += (v2.x + v2.y) + (v2.z + v2.w);
        a3 += (v3.x + v3.y) + (v3.z + v3.w);
    }
    float acc = (a0 + a1) + (a2 + a3);

    #pragma unroll
    for (int off = 16; off > 0; off >>= 1)
        acc += __shfl_xor_sync(0xFFFFFFFFu, acc, off);

    __shared__ float warp_sums[THREADS / 32];
    const int lane = threadIdx.x & 31;
    const int wid  = threadIdx.x >> 5;
    if (lane == 0) warp_sums[wid] = acc;
    __syncthreads();

    if (wid == 0) {
        float s = (lane < THREADS / 32) ? warp_sums[lane] : 0.0f;
        #pragma unroll
        for (int off = 4; off > 0; off >>= 1)
            s += __shfl_xor_sync(0xFFFFFFFFu, s, off);
        if (lane == 0) g_partials[blockIdx.x] = s;
    }
}

// ---------------------------------------------------------------------------
// Phase 2: out[b,o,k] = Y[k] * sum_i coeff[o,i,k] * s[b,i]
// One block per k. m != 0 -> pure zero store (72 of 81 blocks, instant).
// m == 0 -> cooperative, dependency-free staging of coeff[:,:,k] (1024 f)
// and g_partials (1024 f) into smem: 8 independent LDGs per thread, block
// MLP ~2048 -> the whole load phase costs ~one DRAM round-trip.
// ---------------------------------------------------------------------------
__global__ void __launch_bounds__(B_DIM * C_OUT) epilogue_kernel(
        const float* __restrict__ coeff, float* __restrict__ out) {
    const int k  = blockIdx.x;           // 0..80
    const int bo = threadIdx.x;          // 0..255
    const int b  = bo / C_OUT;
    const int o  = bo % C_OUT;

    // l = floor(sqrt(k)); tiny integer search (k <= 80)
    int l = 0;
    while ((l + 1) * (l + 1) <= k) ++l;
    const int m = k - l * l - l;

    if (m != 0) {
        out[((size_t)b * C_OUT + o) * K_SH + k] = 0.0f;
        return;
    }

    __shared__ float s_coeff[C_OUT * C_IN];   // coeff[:,:,k]
    __shared__ float s_part[N_RED_BLOCKS];    // raw partials

    // All 8 loads per thread are independent -> issued back-to-back.
    float c0 = coeff[(size_t)(threadIdx.x + 0 * THREADS) * K_SH + k];
    float c1 = coeff[(size_t)(threadIdx.x + 1 * THREADS) * K_SH + k];
    float c2 = coeff[(size_t)(threadIdx.x + 2 * THREADS) * K_SH + k];
    float c3 = coeff[(size_t)(threadIdx.x + 3 * THREADS) * K_SH + k];
    float4 pp = reinterpret_cast<const float4*>(g_partials)[threadIdx.x];

    s_coeff[threadIdx.x + 0 * THREADS] = c0;
    s_coeff[threadIdx.x + 1 * THREADS] = c1;
    s_coeff[threadIdx.x + 2 * THREADS] = c2;
    s_coeff[threadIdx.x + 3 * THREADS] = c3;
    reinterpret_cast<float4*>(s_part)[threadIdx.x] = pp;
    __syncthreads();

    // Fold SPLITS partials for row bo into a register value via smem,
    // then share: s_rows[row] = sum of its 4 partials.
    __shared__ float s_rows[N_ROWS];
    {
        float s = 0.0f;
        #pragma unroll
        for (int j = 0; j < SPLITS; ++j)
            s += s_part[threadIdx.x * SPLITS + j];
        s_rows[threadIdx.x] = s;
    }
    __syncthreads();

    const float y = sqrtf((2.0f * l + 1.0f) / (4.0f * CUDART_PI_F));
    float acc = 0.0f;
    #pragma unroll
    for (int i = 0; i < C_IN; ++i)
        acc += s_coeff[o * C_IN + i] * s_rows[b * C_IN + i];
    out[((size_t)b * C_OUT + o) * K_SH + k] = y * acc;
}

// ---------------------------------------------------------------------------
extern "C" void kernel_launch(void* const* d_in, const int* in_sizes, int n_in,
                              void* d_out, int out_size) {
    const float* input = (const float*)d_in[0];   // [B, C_in, P]
    const float* coeff = (const float*)d_in[1];   // [C_out, C_in, K]
    float* out = (float*)d_out;                   // [B, C_out, K]

    reduce_kernel<<<N_RED_BLOCKS, THREADS>>>(input);
    epilogue_kernel<<<K_SH, B_DIM * C_OUT>>>(coeff, out);
}

// round 8
// speedup vs baseline: 1.1779x; 1.0307x over previous
#include <cuda_runtime.h>
#include <math_constants.h>

// Problem shapes (from reference setup_inputs)
#define B_DIM 8
#define C_IN 32
#define C_OUT 32
#define P_DIM 262144
#define K_SH 81                         // (MAX_L+1)^2, MAX_L=8
#define N_ROWS (B_DIM * C_IN)           // 256
#define SPLITS 4
#define CHUNK (P_DIM / SPLITS)          // 65536 elements per block (256 KB)
#define THREADS 256
#define N_RED_BLOCKS (N_ROWS * SPLITS)  // 1024

// Scratch (no cudaMalloc allowed)
__device__ float g_partials[N_RED_BLOCKS];

// ---------------------------------------------------------------------------
// Phase 1: per-(row, split) partial sums. 1024 blocks = one full-chip wave.
// Streaming loads (__ldcs: evict-first, no reuse). After the block publishes
// its partial, it signals PDL completion so the dependent epilogue grid's
// griddepcontrol.wait can release as early as possible.
// ---------------------------------------------------------------------------
__global__ void __launch_bounds__(THREADS) reduce_kernel(const float* __restrict__ in) {
    const int row   = blockIdx.x / SPLITS;
    const int split = blockIdx.x % SPLITS;
    const float4* __restrict__ p =
        reinterpret_cast<const float4*>(in + (size_t)row * P_DIM + (size_t)split * CHUNK);

    float a0 = 0.f, a1 = 0.f, a2 = 0.f, a3 = 0.f;
    #pragma unroll 4
    for (int jo = 0; jo < 16; ++jo) {
        float4 v0 = __ldcs(&p[threadIdx.x + (jo * 4 + 0) * THREADS]);
        float4 v1 = __ldcs(&p[threadIdx.x + (jo * 4 + 1) * THREADS]);
        float4 v2 = __ldcs(&p[threadIdx.x + (jo * 4 + 2) * THREADS]);
        float4 v3 = __ldcs(&p[threadIdx.x + (jo * 4 + 3) * THREADS]);
        a0 += (v0.x + v0.y) + (v0.z + v0.w);
        a1 += (v1.x + v1.y) + (v1.z + v1.w);
        a2 += (v2.x + v2.y) + (v2.z + v2.w);
        a3 += (v3.x + v3.y) + (v3.z + v3.w);
    }
    float acc = (a0 + a1) + (a2 + a3);

    #pragma unroll
    for (int off = 16; off > 0; off >>= 1)
        acc += __shfl_xor_sync(0xFFFFFFFFu, acc, off);

    __shared__ float warp_sums[THREADS / 32];
    const int lane = threadIdx.x & 31;
    const int wid  = threadIdx.x >> 5;
    if (lane == 0) warp_sums[wid] = acc;
    __syncthreads();

    if (wid == 0) {
        float s = (lane < THREADS / 32) ? warp_sums[lane] : 0.0f;
        #pragma unroll
        for (int off = 4; off > 0; off >>= 1)
            s += __shfl_xor_sync(0xFFFFFFFFu, s, off);
        if (lane == 0) g_partials[blockIdx.x] = s;
    }
    __syncthreads();   // order the g_partials store before the PDL trigger
    cudaTriggerProgrammaticLaunchCompletion();
}

// ---------------------------------------------------------------------------
// Phase 2 (PDL overlapped): out[b,o,k] = Y[k] * sum_i coeff[o,i,k] * s[b,i]
// Launched with programmatic-stream-serialization: blocks start while the
// reduce is still running. m != 0 blocks write zeros (no dependency).
// m == 0 blocks stage the scattered coeff gather into smem FIRST (overlapped
// with the reduce), then cudaGridDependencySynchronize() before reading
// g_partials.
// ---------------------------------------------------------------------------
__global__ void __launch_bounds__(B_DIM * C_OUT) epilogue_kernel(
        const float* __restrict__ coeff, float* __restrict__ out) {
    const int k  = blockIdx.x;           // 0..80
    const int bo = threadIdx.x;          // 0..255
    const int b  = bo / C_OUT;
    const int o  = bo % C_OUT;

    // l = floor(sqrt(k)); tiny integer search (k <= 80)
    int l = 0;
    while ((l + 1) * (l + 1) <= k) ++l;
    const int m = k - l * l - l;

    if (m != 0) {
        out[((size_t)b * C_OUT + o) * K_SH + k] = 0.0f;
        return;
    }

    // Stage coeff[:,:,k] (independent of the reduce) into smem while the
    // primary grid is still streaming.
    __shared__ float s_coeff[C_OUT * C_IN];
    {
        float c0 = coeff[(size_t)(threadIdx.x + 0 * THREADS) * K_SH + k];
        float c1 = coeff[(size_t)(threadIdx.x + 1 * THREADS) * K_SH + k];
        float c2 = coeff[(size_t)(threadIdx.x + 2 * THREADS) * K_SH + k];
        float c3 = coeff[(size_t)(threadIdx.x + 3 * THREADS) * K_SH + k];
        s_coeff[threadIdx.x + 0 * THREADS] = c0;
        s_coeff[threadIdx.x + 1 * THREADS] = c1;
        s_coeff[threadIdx.x + 2 * THREADS] = c2;
        s_coeff[threadIdx.x + 3 * THREADS] = c3;
    }

    // HW wait for the primary grid (makes its g_partials stores visible).
    cudaGridDependencySynchronize();

    __shared__ float s_part[N_RED_BLOCKS];
    reinterpret_cast<float4*>(s_part)[threadIdx.x] =
        reinterpret_cast<const float4*>(g_partials)[threadIdx.x];
    __syncthreads();

    // s_rows[row] = sum of its SPLITS partials
    __shared__ float s_rows[N_ROWS];
    {
        float s = 0.0f;
        #pragma unroll
        for (int j = 0; j < SPLITS; ++j)
            s += s_part[threadIdx.x * SPLITS + j];
        s_rows[threadIdx.x] = s;
    }
    __syncthreads();

    const float y = sqrtf((2.0f * l + 1.0f) / (4.0f * CUDART_PI_F));
    float acc = 0.0f;
    #pragma unroll
    for (int i = 0; i < C_IN; ++i)
        acc += s_coeff[o * C_IN + i] * s_rows[b * C_IN + i];
    out[((size_t)b * C_OUT + o) * K_SH + k] = y * acc;
}

// ---------------------------------------------------------------------------
extern "C" void kernel_launch(void* const* d_in, const int* in_sizes, int n_in,
                              void* d_out, int out_size) {
    const float* input = (const float*)d_in[0];   // [B, C_in, P]
    const float* coeff = (const float*)d_in[1];   // [C_out, C_in, K]
    float* out = (float*)d_out;                   // [B, C_out, K]

    reduce_kernel<<<N_RED_BLOCKS, THREADS>>>(input);

    // Epilogue with programmatic dependent launch: overlaps its launch and
    // coeff gather with the reduce; griddepsync provides the real dependency.
    cudaLaunchConfig_t cfg = {};
    cfg.gridDim  = dim3(K_SH, 1, 1);
    cfg.blockDim = dim3(B_DIM * C_OUT, 1, 1);
    cudaLaunchAttribute attrs[1];
    attrs[0].id = cudaLaunchAttributeProgrammaticStreamSerialization;
    attrs[0].val.programmaticStreamSerializationAllowed = 1;
    cfg.attrs = attrs;
    cfg.numAttrs = 1;
    cudaLaunchKernelEx(&cfg, epilogue_kernel, coeff, out);
}

// round 11
// speedup vs baseline: 1.1854x; 1.0063x over previous
#include <cuda_runtime.h>
#include <math_constants.h>

// Problem shapes (from reference setup_inputs)
#define B_DIM 8
#define C_IN 32
#define C_OUT 32
#define P_DIM 262144
#define K_SH 81                         // (MAX_L+1)^2, MAX_L=8
#define N_ROWS (B_DIM * C_IN)           // 256
#define SPLITS 4
#define CHUNK (P_DIM / SPLITS)          // 65536 elements per block (256 KB)
#define THREADS 256
#define N_RED_BLOCKS (N_ROWS * SPLITS)  // 1024

// Scratch (no cudaMalloc allowed)
__device__ float g_partials[N_RED_BLOCKS];

// ---------------------------------------------------------------------------
// Phase 1: per-(row, split) partial sums. 1024 blocks = one full-chip wave.
// PDL trigger fires at the START of each block: it only gates the secondary
// grid's LAUNCH (data safety comes from griddepcontrol.wait in the epilogue,
// which waits for this entire grid's completion). This lets the epilogue's
// zero-stores and coeff gathers run concurrently with the 40us stream.
// ---------------------------------------------------------------------------
__global__ void __launch_bounds__(THREADS) reduce_kernel(const float* __restrict__ in) {
    cudaTriggerProgrammaticLaunchCompletion();

    const int row   = blockIdx.x / SPLITS;
    const int split = blockIdx.x % SPLITS;
    const float4* __restrict__ p =
        reinterpret_cast<const float4*>(in + (size_t)row * P_DIM + (size_t)split * CHUNK);

    float a0 = 0.f, a1 = 0.f, a2 = 0.f, a3 = 0.f;
    #pragma unroll 4
    for (int jo = 0; jo < 16; ++jo) {
        float4 v0 = __ldcs(&p[threadIdx.x + (jo * 4 + 0) * THREADS]);
        float4 v1 = __ldcs(&p[threadIdx.x + (jo * 4 + 1) * THREADS]);
        float4 v2 = __ldcs(&p[threadIdx.x + (jo * 4 + 2) * THREADS]);
        float4 v3 = __ldcs(&p[threadIdx.x + (jo * 4 + 3) * THREADS]);
        a0 += (v0.x + v0.y) + (v0.z + v0.w);
        a1 += (v1.x + v1.y) + (v1.z + v1.w);
        a2 += (v2.x + v2.y) + (v2.z + v2.w);
        a3 += (v3.x + v3.y) + (v3.z + v3.w);
    }
    float acc = (a0 + a1) + (a2 + a3);

    #pragma unroll
    for (int off = 16; off > 0; off >>= 1)
        acc += __shfl_xor_sync(0xFFFFFFFFu, acc, off);

    __shared__ float warp_sums[THREADS / 32];
    const int lane = threadIdx.x & 31;
    const int wid  = threadIdx.x >> 5;
    if (lane == 0) warp_sums[wid] = acc;
    __syncthreads();

    if (wid == 0) {
        float s = (lane < THREADS / 32) ? warp_sums[lane] : 0.0f;
        #pragma unroll
        for (int off = 4; off > 0; off >>= 1)
            s += __shfl_xor_sync(0xFFFFFFFFu, s, off);
        if (lane == 0) g_partials[blockIdx.x] = s;
    }
}

// ---------------------------------------------------------------------------
// Phase 2 (PDL overlapped): out[b,o,k] = Y[k] * sum_i coeff[o,i,k] * s[b,i]
// Launches while the reduce streams. m != 0 blocks write zeros and retire
// (no dependency at all). m == 0 blocks gather coeff[:,:,k] into smem
// (independent of the reduce), then griddepcontrol.wait for the reduce grid,
// then a short L2-hot + smem tail.
// ---------------------------------------------------------------------------
__global__ void __launch_bounds__(B_DIM * C_OUT) epilogue_kernel(
        const float* __restrict__ coeff, float* __restrict__ out) {
    const int k  = blockIdx.x;           // 0..80
    const int bo = threadIdx.x;          // 0..255
    const int b  = bo / C_OUT;
    const int o  = bo % C_OUT;

    // l = floor(sqrt(k)); tiny integer search (k <= 80)
    int l = 0;
    while ((l + 1) * (l + 1) <= k) ++l;
    const int m = k - l * l - l;

    if (m != 0) {
        out[((size_t)b * C_OUT + o) * K_SH + k] = 0.0f;
        return;
    }

    // Stage coeff[:,:,k] into smem while the primary grid is still streaming.
    __shared__ float s_coeff[C_OUT * C_IN];
    {
        float c0 = coeff[(size_t)(threadIdx.x + 0 * THREADS) * K_SH + k];
        float c1 = coeff[(size_t)(threadIdx.x + 1 * THREADS) * K_SH + k];
        float c2 = coeff[(size_t)(threadIdx.x + 2 * THREADS) * K_SH + k];
        float c3 = coeff[(size_t)(threadIdx.x + 3 * THREADS) * K_SH + k];
        s_coeff[threadIdx.x + 0 * THREADS] = c0;
        s_coeff[threadIdx.x + 1 * THREADS] = c1;
        s_coeff[threadIdx.x + 2 * THREADS] = c2;
        s_coeff[threadIdx.x + 3 * THREADS] = c3;
    }

    // HW wait for the primary grid (makes its g_partials stores visible).
    cudaGridDependencySynchronize();

    __shared__ float s_part[N_RED_BLOCKS];
    reinterpret_cast<float4*>(s_part)[threadIdx.x] =
        reinterpret_cast<const float4*>(g_partials)[threadIdx.x];
    __syncthreads();

    // s_rows[row] = sum of its SPLITS partials
    __shared__ float s_rows[N_ROWS];
    {
        float s = 0.0f;
        #pragma unroll
        for (int j = 0; j < SPLITS; ++j)
            s += s_part[threadIdx.x * SPLITS + j];
        s_rows[threadIdx.x] = s;
    }
    __syncthreads();

    const float y = sqrtf((2.0f * l + 1.0f) / (4.0f * CUDART_PI_F));
    float acc = 0.0f;
    #pragma unroll
    for (int i = 0; i < C_IN; ++i)
        acc += s_coeff[o * C_IN + i] * s_rows[b * C_IN + i];
    out[((size_t)b * C_OUT + o) * K_SH + k] = y * acc;
}

// ---------------------------------------------------------------------------
extern "C" void kernel_launch(void* const* d_in, const int* in_sizes, int n_in,
                              void* d_out, int out_size) {
    const float* input = (const float*)d_in[0];   // [B, C_in, P]
    const float* coeff = (const float*)d_in[1];   // [C_out, C_in, K]
    float* out = (float*)d_out;                   // [B, C_out, K]

    reduce_kernel<<<N_RED_BLOCKS, THREADS>>>(input);

    // Epilogue with programmatic dependent launch: its launch, zero-stores,
    // and coeff gathers overlap the reduce; griddepsync is the dependency.
    cudaLaunchConfig_t cfg = {};
    cfg.gridDim  = dim3(K_SH, 1, 1);
    cfg.blockDim = dim3(B_DIM * C_OUT, 1, 1);
    cudaLaunchAttribute attrs[1];
    attrs[0].id = cudaLaunchAttributeProgrammaticStreamSerialization;
    attrs[0].val.programmaticStreamSerializationAllowed = 1;
    cfg.attrs = attrs;
    cfg.numAttrs = 1;
    cudaLaunchKernelEx(&cfg, epilogue_kernel, coeff, out);
}